// round 16
// baseline (speedup 1.0000x reference)
#include <cuda_runtime.h>
#include <math.h>
#include <stdint.h>

// PotentialLoss: condensation loss, N hits x P particles, D=8.
// Inputs: w[N] f32, beta[N] f32, x[N*8] f32, y[N] f32, particle_id[N] i32
// Output: scalar f32 = sum_p mean_i q_i (M*va + 10*(1-M)*vr)
//
// Tensor-core screen: S = X @ Xa^T via mma.sync m16n8k8 bf16 (128 pairs/instr).
// Conservative fire test  d > thr_col + rx_row, thr = 0.5*(SCL*xxa - TM),
// rx = 0.5*SCL*xx  (equivalent to SCL*(xx+xxa) - 2d < TM; implied by exact
// sq < 1 given bf16 input rounding, margin ~1e-2). Fired row-tiles take a
// warp-UNIFORM mask walk recomputing exact fp32; all rare-path data (exact
// rows, q, th) is loaded ONLY inside the fired branch.

#define PP 512
#define TILE 128
#define NTILE (PP / TILE)      // 4
#define NMAX 262144
#define QMIN 0.01f
#define REP_SCALE 10.0f
#define MSTRIDE 32
#define TM 1.06f
#define SCL 0.995f

__device__ float              g_q[NMAX];
__device__ float              g_xx[NMAX];
__device__ unsigned           g_xb[NMAX * 4];   // bf16x2-packed x rows (4 u32/row)
__device__ unsigned long long g_m[PP * MSTRIDE];
__device__ double             g_acc;
__device__ unsigned           g_tick;

typedef unsigned long long ull;

__device__ __forceinline__ unsigned bf16pair(float lo, float hi) {
    unsigned r;
    asm("cvt.rn.bf16x2.f32 %0, %1, %2;" : "=r"(r) : "f"(hi), "f"(lo));
    return r;
}
__device__ __forceinline__ float sqrt_ap(float s) {
    float r;
    asm("sqrt.approx.f32 %0, %1;" : "=f"(r) : "f"(s));
    return r;
}
// Exact fp32 dot, FIXED op order — shared by rare path, fixup, table build.
__device__ __forceinline__ float dot8(const float* a, const float* b) {
    float s = a[0] * b[0];
#pragma unroll
    for (int k = 1; k < 8; ++k) s = fmaf(a[k], b[k], s);
    return s;
}
__device__ __forceinline__ void mma_bf16(float& d0, float& d1, float& d2, float& d3,
                                         unsigned a0, unsigned a1, unsigned b0) {
    float z = 0.f;
    asm("mma.sync.aligned.m16n8k8.row.col.f32.bf16.bf16.f32 "
        "{%0,%1,%2,%3},{%4,%5},{%6},{%7,%8,%9,%10};"
        : "=f"(d0), "=f"(d1), "=f"(d2), "=f"(d3)
        : "r"(a0), "r"(a1), "r"(b0), "f"(z), "f"(z), "f"(z), "f"(z));
}

// Pass 1: q + 64-bit argmax per particle; also bf16-pack x rows and stash xx.
// Rows [n, npad) clone row 0 with q=0 (never contribute).
__global__ void k_qmax(const float* __restrict__ beta, const float* __restrict__ x,
                       const int* __restrict__ pid, int n, int npad) {
    int i = blockIdx.x * 256 + threadIdx.x;
    if (i == 0) g_acc = 0.0;
    if (i >= npad) return;
    int src = (i < n) ? i : 0;
    const float4* xr = (const float4*)(x + (size_t)src * 8);
    float4 f0 = xr[0], f1 = xr[1];
    float v[8] = {f0.x, f0.y, f0.z, f0.w, f1.x, f1.y, f1.z, f1.w};
    g_xx[i] = dot8(v, v);
    uint4 b;
    b.x = bf16pair(f0.x, f0.y);
    b.y = bf16pair(f0.z, f0.w);
    b.z = bf16pair(f1.x, f1.y);
    b.w = bf16pair(f1.z, f1.w);
    ((uint4*)g_xb)[i] = b;
    if (i < n) {
        float a = atanhf(beta[i]);
        float q = a * a + QMIN;
        g_q[i] = q;
        ull m = ((ull)__float_as_uint(q) << 32) | (ull)(0xffffffffu - (unsigned)i);
        atomicMax(&g_m[(unsigned)pid[i] * MSTRIDE], m);
    } else {
        g_q[i] = 0.f;
    }
}

// Pass 2: grid (chunks x NTILE), 128 threads = 4 warps; warp owns 64 hits
// as 4 m16 row-tiles vs the block's 128-particle tile.
__global__ void __launch_bounds__(128, 8) k_main(const float* __restrict__ x,
                                                 const int* __restrict__ pid,
                                                 float* __restrict__ out,
                                                 int n, int nbTotal) {
    __shared__ unsigned sXb[TILE * 4];   // bf16 dims, word w = dims {2w,2w+1}
    __shared__ float    sThr[TILE];      // 0.5*(SCL*xxa - TM) per particle
    __shared__ float    sF[TILE * 12];   // fp32: dims[0..7], xxa, 10qa, qa, pad
    __shared__ float    wsum[4];

    const int base = blockIdx.y * TILE;
    const int tid = threadIdx.x;

    // Table build: one thread per particle (L2-hot gathers).
    {
        int p = base + tid;
        ull m = g_m[(unsigned)p * MSTRIDE];
        unsigned qb = (unsigned)(m >> 32);
        bool valid = (qb != 0u) && (p != 0);
        int a = qb ? (int)(0xffffffffu - (unsigned)(m & 0xffffffffu)) : 0;
        const float4* xr = (const float4*)(x + (size_t)a * 8);
        float4 A = xr[0], B = xr[1];
        float dv[8] = {A.x, A.y, A.z, A.w, B.x, B.y, B.z, B.w};
        float xxa = dot8(dv, dv);
        float qa = valid ? __uint_as_float(qb) : 0.0f;
        float* F = &sF[tid * 12];
#pragma unroll
        for (int k = 0; k < 8; ++k) F[k] = dv[k];
        F[8] = xxa;
        F[9] = REP_SCALE * qa;
        F[10] = qa;
        sThr[tid] = 0.5f * (SCL * xxa - TM);
        sXb[tid * 4 + 0] = bf16pair(A.x, A.y);
        sXb[tid * 4 + 1] = bf16pair(A.z, A.w);
        sXb[tid * 4 + 2] = bf16pair(B.x, B.y);
        sXb[tid * 4 + 3] = bf16pair(B.z, B.w);
    }
    __syncthreads();

    const int w = tid >> 5;
    const int lane = tid & 31;
    const int g = lane >> 2;
    const int qd = lane & 3;
    float S = 0.f;   // repulsive accumulation (q-weighted)

    // 4 row-tiles of 16 hits per warp.
#pragma unroll 1
    for (int rt = 0; rt < 4; ++rt) {
        int hb = blockIdx.x * 256 + w * 64 + rt * 16;
        int h0 = hb + g, h1 = hb + g + 8;

        unsigned a0 = g_xb[h0 * 4 + qd];
        unsigned a1 = g_xb[h1 * 4 + qd];
        float xx0 = g_xx[h0], xx1 = g_xx[h1];
        float rx0 = 0.5f * SCL * xx0;      // fire: d > thr_col + rx_row
        float rx1 = 0.5f * SCL * xx1;

        unsigned fm = 0;
#pragma unroll
        for (int j = 0; j < 16; ++j) {
            unsigned b0 = sXb[(j * 8 + g) * 4 + qd];
            float d0, d1, d2, d3;
            mma_bf16(d0, d1, d2, d3, a0, a1, b0);
            float2 thr = *(const float2*)&sThr[j * 8 + qd * 2];
            float t0 = thr.x + rx0, t1 = thr.y + rx0;
            float t2 = thr.x + rx1, t3 = thr.y + rx1;
            bool f = (d0 > t0) | (d1 > t1) | (d2 > t2) | (d3 > t3);
            fm |= ((unsigned)f) << j;
        }

        unsigned um = __reduce_or_sync(0xffffffffu, fm);   // warp-uniform
        if (um) {
            // Rare: load exact rows + q + thresholds only now.
            int s0 = (h0 < n) ? h0 : 0, s1 = (h1 < n) ? h1 : 0;
            float4 Xa = ((const float4*)(x + (size_t)s0 * 8))[0];
            float4 Xb = ((const float4*)(x + (size_t)s0 * 8))[1];
            float4 Ya = ((const float4*)(x + (size_t)s1 * 8))[0];
            float4 Yb = ((const float4*)(x + (size_t)s1 * 8))[1];
            float XR0[8] = {Xa.x, Xa.y, Xa.z, Xa.w, Xb.x, Xb.y, Xb.z, Xb.w};
            float XR1[8] = {Ya.x, Ya.y, Ya.z, Ya.w, Yb.x, Yb.y, Yb.z, Yb.w};
            float th0 = 1.f - xx0, th1 = 1.f - xx1;
            float q0 = g_q[h0], q1 = g_q[h1];
            do {
                int j = __ffs(um) - 1;
                um &= um - 1;
                const float* F0 = &sF[(j * 8 + qd * 2) * 12];
                const float* F1 = F0 + 12;
                float c = fmaf(-2.f, dot8(XR0, F0), F0[8]);
                if (c < th0) S += q0 * F0[9] * (1.f - sqrt_ap(fmaxf(xx0 + c, 0.f)));
                c = fmaf(-2.f, dot8(XR0, F1), F1[8]);
                if (c < th0) S += q0 * F1[9] * (1.f - sqrt_ap(fmaxf(xx0 + c, 0.f)));
                c = fmaf(-2.f, dot8(XR1, F0), F0[8]);
                if (c < th1) S += q1 * F0[9] * (1.f - sqrt_ap(fmaxf(xx1 + c, 0.f)));
                c = fmaf(-2.f, dot8(XR1, F1), F1[8]);
                if (c < th1) S += q1 * F1[9] * (1.f - sqrt_ap(fmaxf(xx1 + c, 0.f)));
            } while (um);
        }
    }

    // Self-particle fixup: swap repulsive for attractive, identical helpers
    // (same dot8 op order, same c and th) => identical fire condition.
    float contrib = S;
#pragma unroll
    for (int hh = 0; hh < 2; ++hh) {
        int i = blockIdx.x * 256 + tid + hh * 128;
        if (i < n) {
            int mp = pid[i] - base;
            if ((unsigned)mp < TILE) {
                const float4* xr = (const float4*)(x + (size_t)i * 8);
                float4 f0 = xr[0], f1 = xr[1];
                float xv[8] = {f0.x, f0.y, f0.z, f0.w, f1.x, f1.y, f1.z, f1.w};
                float xx = g_xx[i];
                float th = 1.f - xx;
                const float* F = &sF[mp * 12];
                float c = fmaf(-2.f, dot8(xv, F), F[8]);
                float sq = fmaxf(xx + c, 0.f);
                float q = g_q[i];
                float rfix = (c < th) ? q * F[9] * (1.f - sqrt_ap(sq)) : 0.f;
                contrib += q * F[10] * sq - rfix;
            }
        }
    }

    // Block reduction -> one double atomic per block.
#pragma unroll
    for (int o = 16; o > 0; o >>= 1)
        contrib += __shfl_down_sync(0xffffffffu, contrib, o);
    if ((tid & 31) == 0) wsum[tid >> 5] = contrib;
    __syncthreads();
    if (tid == 0) {
        atomicAdd(&g_acc, (double)(wsum[0] + wsum[1] + wsum[2] + wsum[3]));
        __threadfence();
        unsigned old = atomicInc(&g_tick, (unsigned)nbTotal - 1u);
        if (old == (unsigned)nbTotal - 1u) {
            double total = atomicAdd(&g_acc, 0.0);
            out[0] = (float)(total / (double)n);
        }
    }
}

extern "C" void kernel_launch(void* const* d_in, const int* in_sizes, int n_in,
                              void* d_out, int out_size) {
    const float* beta = (const float*)d_in[1];
    const float* x    = (const float*)d_in[2];
    const int*   pid  = (const int*)d_in[4];
    int n = in_sizes[1];

    int chunks = (n + 255) / 256;
    int npad = chunks * 256;
    dim3 grid(chunks, NTILE);
    k_qmax<<<chunks, 256>>>(beta, x, pid, n, npad);
    k_main<<<grid, 128>>>(x, pid, (float*)d_out, n, chunks * NTILE);
}

// round 17
// speedup vs baseline: 1.0088x; 1.0088x over previous
#include <cuda_runtime.h>
#include <math.h>
#include <stdint.h>

// PotentialLoss: condensation loss, N hits x P particles, D=8.
// Inputs: w[N] f32, beta[N] f32, x[N*8] f32, y[N] f32, particle_id[N] i32
// Output: scalar f32 = sum_p mean_i q_i (M*va + 10*(1-M)*vr)
//
// Tensor-core screen: S = X @ Xa^T via mma.sync m16n8k8 bf16 (128 pairs/instr).
// Conservative fire test  d > thr_col + rx_row  (== SCL*(xx+xxa) - 2d < TM,
// implied by exact sq < 1 given bf16 input rounding). k_main is LDG-free
// after a staged prologue: hit rows/xx/q live in shared, so the rare walk
// and fixup are pure LDS+FMA with no long-scoreboard stalls.

#define PP 512
#define TILE 128
#define NTILE (PP / TILE)      // 4
#define NMAX 262144
#define QMIN 0.01f
#define REP_SCALE 10.0f
#define MSTRIDE 32
#define TM 1.01f
#define SCL 0.9955f

__device__ float              g_q[NMAX];
__device__ float              g_xx[NMAX];
__device__ unsigned           g_xb[NMAX * 4];   // bf16x2-packed x rows (4 u32/row)
__device__ unsigned long long g_m[PP * MSTRIDE];
__device__ double             g_acc;
__device__ unsigned           g_tick;

typedef unsigned long long ull;

__device__ __forceinline__ unsigned bf16pair(float lo, float hi) {
    unsigned r;
    asm("cvt.rn.bf16x2.f32 %0, %1, %2;" : "=r"(r) : "f"(hi), "f"(lo));
    return r;
}
__device__ __forceinline__ float sqrt_ap(float s) {
    float r;
    asm("sqrt.approx.f32 %0, %1;" : "=f"(r) : "f"(s));
    return r;
}
// Exact fp32 dot, FIXED op order — shared by rare walk, fixup, table build.
__device__ __forceinline__ float dot8(const float* a, const float* b) {
    float s = a[0] * b[0];
#pragma unroll
    for (int k = 1; k < 8; ++k) s = fmaf(a[k], b[k], s);
    return s;
}
__device__ __forceinline__ void mma_bf16(float& d0, float& d1, float& d2, float& d3,
                                         unsigned a0, unsigned a1, unsigned b0) {
    float z = 0.f;
    asm("mma.sync.aligned.m16n8k8.row.col.f32.bf16.bf16.f32 "
        "{%0,%1,%2,%3},{%4,%5},{%6},{%7,%8,%9,%10};"
        : "=f"(d0), "=f"(d1), "=f"(d2), "=f"(d3)
        : "r"(a0), "r"(a1), "r"(b0), "f"(z), "f"(z), "f"(z), "f"(z));
}

// Pass 1: q + 64-bit argmax per particle; also bf16-pack x rows and stash xx.
// Rows [n, npad) clone row 0 with q = 0 (never contribute).
__global__ void k_qmax(const float* __restrict__ beta, const float* __restrict__ x,
                       const int* __restrict__ pid, int n, int npad) {
    int i = blockIdx.x * 256 + threadIdx.x;
    if (i == 0) g_acc = 0.0;
    if (i >= npad) return;
    int src = (i < n) ? i : 0;
    const float4* xr = (const float4*)(x + (size_t)src * 8);
    float4 f0 = xr[0], f1 = xr[1];
    float v[8] = {f0.x, f0.y, f0.z, f0.w, f1.x, f1.y, f1.z, f1.w};
    g_xx[i] = dot8(v, v);
    uint4 b;
    b.x = bf16pair(f0.x, f0.y);
    b.y = bf16pair(f0.z, f0.w);
    b.z = bf16pair(f1.x, f1.y);
    b.w = bf16pair(f1.z, f1.w);
    ((uint4*)g_xb)[i] = b;
    if (i < n) {
        float a = atanhf(beta[i]);
        float q = a * a + QMIN;
        g_q[i] = q;
        ull m = ((ull)__float_as_uint(q) << 32) | (ull)(0xffffffffu - (unsigned)i);
        atomicMax(&g_m[(unsigned)pid[i] * MSTRIDE], m);
    } else {
        g_q[i] = 0.f;
    }
}

// Pass 2: grid (chunks x NTILE), 128 threads = 4 warps; warp owns 64 hits
// as 4 m16 row-tiles vs the block's 128-particle tile.
__global__ void __launch_bounds__(128, 8) k_main(const float* __restrict__ x,
                                                 const int* __restrict__ pid,
                                                 float* __restrict__ out,
                                                 int n, int nbTotal) {
    __shared__ unsigned sXb[TILE * 4];    // bf16 particle dims
    __shared__ float    sThr[TILE];       // 0.5*(SCL*xxa - TM)
    __shared__ float    sF[TILE * 12];    // fp32 particle: dims[8], xxa, 10qa, qa
    __shared__ float    sX[256 * 12];     // fp32 hit rows (stride 12 for banks)
    __shared__ float    sXX[256];         // exact xx per hit
    __shared__ float    sQ[256];          // q per hit (0 for pads)
    __shared__ float    wsum[4];

    const int base = blockIdx.y * TILE;
    const int tid = threadIdx.x;
    const int w = tid >> 5;
    const int lane = tid & 31;
    const int g = lane >> 2;
    const int qd = lane & 3;

    // Hoist ALL hot-loop LDGs now (independent of shared; MLP=8).
    unsigned A0[4], A1[4];
    const int hbase = blockIdx.x * 256 + w * 64;
#pragma unroll
    for (int rt = 0; rt < 4; ++rt) {
        A0[rt] = g_xb[(hbase + rt * 16 + g) * 4 + qd];
        A1[rt] = g_xb[(hbase + rt * 16 + g + 8) * 4 + qd];
    }

    // Particle table: one thread per particle (L2-hot gathers).
    {
        int p = base + tid;
        ull m = g_m[(unsigned)p * MSTRIDE];
        unsigned qb = (unsigned)(m >> 32);
        bool valid = (qb != 0u) && (p != 0);
        int a = qb ? (int)(0xffffffffu - (unsigned)(m & 0xffffffffu)) : 0;
        const float4* xr = (const float4*)(x + (size_t)a * 8);
        float4 A = xr[0], B = xr[1];
        float dv[8] = {A.x, A.y, A.z, A.w, B.x, B.y, B.z, B.w};
        float xxa = dot8(dv, dv);
        float qa = valid ? __uint_as_float(qb) : 0.0f;
        float* F = &sF[tid * 12];
#pragma unroll
        for (int k = 0; k < 8; ++k) F[k] = dv[k];
        F[8] = xxa;
        F[9] = REP_SCALE * qa;
        F[10] = qa;
        sThr[tid] = 0.5f * (SCL * xxa - TM);
        sXb[tid * 4 + 0] = bf16pair(A.x, A.y);
        sXb[tid * 4 + 1] = bf16pair(A.z, A.w);
        sXb[tid * 4 + 2] = bf16pair(B.x, B.y);
        sXb[tid * 4 + 3] = bf16pair(B.z, B.w);
    }

    // Stage this block's 256 hit rows + xx + q into shared.
#pragma unroll
    for (int hh = 0; hh < 2; ++hh) {
        int r = tid + hh * 128;
        int i = blockIdx.x * 256 + r;
        int src = (i < n) ? i : 0;                 // i < npad always
        const float4* xr = (const float4*)(x + (size_t)src * 8);
        *(float4*)&sX[r * 12] = xr[0];
        *(float4*)&sX[r * 12 + 4] = xr[1];
        sXX[r] = g_xx[i];
        sQ[r] = g_q[i];                            // 0 for pad rows
    }
    __syncthreads();

    float S = 0.f;   // repulsive accumulation (q-weighted)

#pragma unroll 1
    for (int rt = 0; rt < 4; ++rt) {
        int r0 = w * 64 + rt * 16 + g;   // local row indices
        int r1 = r0 + 8;
        float xx0 = sXX[r0], xx1 = sXX[r1];
        float rx0 = 0.5f * SCL * xx0;    // fire: d > thr_col + rx_row
        float rx1 = 0.5f * SCL * xx1;
        unsigned a0 = A0[rt], a1 = A1[rt];

        unsigned fm = 0;
#pragma unroll
        for (int j = 0; j < 16; ++j) {
            unsigned b0 = sXb[(j * 8 + g) * 4 + qd];
            float d0, d1, d2, d3;
            mma_bf16(d0, d1, d2, d3, a0, a1, b0);
            float2 thr = *(const float2*)&sThr[j * 8 + qd * 2];
            bool f = (d0 > thr.x + rx0) | (d1 > thr.y + rx0)
                   | (d2 > thr.x + rx1) | (d3 > thr.y + rx1);
            fm |= ((unsigned)f) << j;
        }

        unsigned um = __reduce_or_sync(0xffffffffu, fm);   // warp-uniform
        if (um) {
            float XR0[8], XR1[8];
#pragma unroll
            for (int k = 0; k < 8; ++k) {
                XR0[k] = sX[r0 * 12 + k];
                XR1[k] = sX[r1 * 12 + k];
            }
            float th0 = 1.f - xx0, th1 = 1.f - xx1;
            float q0 = sQ[r0], q1 = sQ[r1];
            do {
                int j = __ffs(um) - 1;
                um &= um - 1;
                const float* F0 = &sF[(j * 8 + qd * 2) * 12];
                const float* F1 = F0 + 12;
                float c = fmaf(-2.f, dot8(XR0, F0), F0[8]);
                if (c < th0) S += q0 * F0[9] * (1.f - sqrt_ap(fmaxf(xx0 + c, 0.f)));
                c = fmaf(-2.f, dot8(XR0, F1), F1[8]);
                if (c < th0) S += q0 * F1[9] * (1.f - sqrt_ap(fmaxf(xx0 + c, 0.f)));
                c = fmaf(-2.f, dot8(XR1, F0), F0[8]);
                if (c < th1) S += q1 * F0[9] * (1.f - sqrt_ap(fmaxf(xx1 + c, 0.f)));
                c = fmaf(-2.f, dot8(XR1, F1), F1[8]);
                if (c < th1) S += q1 * F1[9] * (1.f - sqrt_ap(fmaxf(xx1 + c, 0.f)));
            } while (um);
        }
    }

    // Self-particle fixup: swap repulsive for attractive, identical helpers
    // (same dot8 on the same sX/sF values, same c and th) => identical fire set.
    float contrib = S;
#pragma unroll
    for (int hh = 0; hh < 2; ++hh) {
        int r = tid + hh * 128;
        int i = blockIdx.x * 256 + r;
        if (i < n) {
            int mp = pid[i] - base;
            if ((unsigned)mp < TILE) {
                const float* XV = &sX[r * 12];
                float xx = sXX[r];
                float th = 1.f - xx;
                const float* F = &sF[mp * 12];
                float c = fmaf(-2.f, dot8(XV, F), F[8]);
                float sq = fmaxf(xx + c, 0.f);
                float q = sQ[r];
                float rfix = (c < th) ? q * F[9] * (1.f - sqrt_ap(sq)) : 0.f;
                contrib += q * F[10] * sq - rfix;
            }
        }
    }

    // Block reduction -> one double atomic per block.
#pragma unroll
    for (int o = 16; o > 0; o >>= 1)
        contrib += __shfl_down_sync(0xffffffffu, contrib, o);
    if ((tid & 31) == 0) wsum[tid >> 5] = contrib;
    __syncthreads();
    if (tid == 0) {
        atomicAdd(&g_acc, (double)(wsum[0] + wsum[1] + wsum[2] + wsum[3]));
        __threadfence();
        unsigned old = atomicInc(&g_tick, (unsigned)nbTotal - 1u);
        if (old == (unsigned)nbTotal - 1u) {
            double total = atomicAdd(&g_acc, 0.0);
            out[0] = (float)(total / (double)n);
        }
    }
}

extern "C" void kernel_launch(void* const* d_in, const int* in_sizes, int n_in,
                              void* d_out, int out_size) {
    const float* beta = (const float*)d_in[1];
    const float* x    = (const float*)d_in[2];
    const int*   pid  = (const int*)d_in[4];
    int n = in_sizes[1];

    int chunks = (n + 255) / 256;
    int npad = chunks * 256;
    dim3 grid(chunks, NTILE);
    k_qmax<<<chunks, 256>>>(beta, x, pid, n, npad);
    k_main<<<grid, 128>>>(x, pid, (float*)d_out, n, chunks * NTILE);
}